// round 11
// baseline (speedup 1.0000x reference)
#include <cuda_runtime.h>
#include <cstdint>
#include <cstddef>

#define TSTEPS 32
#define INF    27
#define HID    10

__device__ __forceinline__ void cp8(uint32_t saddr, const void* gptr){
  asm volatile("cp.async.ca.shared.global [%0], [%1], 8;" :: "r"(saddr), "l"(gptr));
}
// single-instruction tanh (MUFU.TANH, sm_75+)
__device__ __forceinline__ float tanh_fast(float x){
  float r;
  asm("tanh.approx.f32 %0, %1;" : "=f"(r) : "f"(x));
  return r;
}
// sigmoid from a PRE-HALVED preactivation: acc already holds x/2
//   sigma(x) = 0.5 + 0.5*tanh(x/2)  -> 1 MUFU + 1 FMA
__device__ __forceinline__ float sig_from_half(float acc_half){
  return fmaf(0.5f, tanh_fast(acc_half), 0.5f);
}

// SINGLE-WARP blocks: 32 threads, 32 batch elements per block, 2048 blocks.
// Lane pairs (2p, 2p+1) share batch elements {2p, 2p+1}; lane parity selects
// which 5 hidden units it computes (split-k). No __syncthreads anywhere in
// the recurrence (warp-synchronous); 13.8 blocks/SM -> 7% tail imbalance.
__global__ void __launch_bounds__(32, 16) lstm_fused_kernel(
    const float* __restrict__ word,
    const float* __restrict__ W_ih, const float* __restrict__ W_hh,
    const float* __restrict__ b_ih, const float* __restrict__ b_hh,
    const float* __restrict__ W_fc, const float* __restrict__ b_fc,
    const float* __restrict__ W_out, const float* __restrict__ b_out,
    float* __restrict__ out, int Bn)
{
  // scalar weights, rows padded for LDS.128-friendly immediate offsets.
  // Gate row order r in [0,40): [0,10)=i, [10,20)=f, [20,30)=g, [30,40)=o.
  // i/f/o rows stored pre-multiplied by 0.5 (sigmoid-via-tanh identity).
  __shared__ __align__(16) float s_wih[40*28];  // row r: r*28 + j, j<27, pad 0
  __shared__ __align__(16) float s_whh[40*12];  // row r: r*12 + j, j<10, pad 0
  __shared__ float s_bias[40];                  // (b_ih + b_hh), i/f/o halved
  __shared__ float s_wfc[50], s_bfc[5], s_wout[5], s_bout[1];
  __shared__ __align__(16) float s_x[2][32*INF];   // double-buffered x staging

  const int tid  = threadIdx.x;        // 0..31 (single warp)
  const int half = tid & 1;            // which 5 k's this lane owns
  const int p    = tid >> 1;           // pair index (0..15)
  const int kb   = half * 5;

  for (int idx = tid; idx < 40*28; idx += 32){
    int r = idx / 28, j = idx - r*28;
    float sc = (r < 20 || r >= 30) ? 0.5f : 1.0f;   // halve i,f,o rows
    s_wih[idx] = (j < 27) ? sc * W_ih[r*27 + j] : 0.f;
  }
  for (int idx = tid; idx < 40*12; idx += 32){
    int r = idx / 12, j = idx - r*12;
    float sc = (r < 20 || r >= 30) ? 0.5f : 1.0f;
    s_whh[idx] = (j < 10) ? sc * W_hh[r*10 + j] : 0.f;
  }
  for (int idx = tid; idx < 40; idx += 32){
    float sc = (idx < 20 || idx >= 30) ? 0.5f : 1.0f;
    s_bias[idx] = sc * (b_ih[idx] + b_hh[idx]);
  }
  for (int idx = tid; idx < 50; idx += 32) s_wfc[idx] = W_fc[idx];
  if (tid < 5) { s_bfc[tid] = b_fc[tid]; s_wout[tid] = W_out[tid]; }
  if (tid == 0) s_bout[0] = b_out[0];
  __syncwarp();    // weights visible (single warp -> warp sync suffices)

  const int blockElem = blockIdx.x * 32;
  const uint32_t sx0 = (uint32_t)__cvta_generic_to_shared(&s_x[0][0]);

  // stage t=0 into buffer 0 (432 float2 per block-step, 32 threads)
  {
    const float2* src = (const float2*)(word + ((size_t)blockElem) * INF);
    #pragma unroll
    for (int m = 0; m < 14; m++){
      int i2 = m*32 + tid;
      if (i2 < 432) cp8(sx0 + (uint32_t)(i2*8), src + i2);
    }
    asm volatile("cp.async.commit_group;");
  }

  // full h for both elements (rebuilt each step via shfl exchange),
  // own-c only (5 k x 2 elems)
  float hA[10], hB[10], cA[5], cB[5];
  #pragma unroll
  for (int k = 0; k < 10; k++){ hA[k]=0.f; hB[k]=0.f; }
  #pragma unroll
  for (int k = 0; k < 5;  k++){ cA[k]=0.f; cB[k]=0.f; }

  // lane-local weight bases (kb is uniform per lane; hoisted out of the loop)
  const float* wih_b  = s_wih + kb*28;
  const float* whh_b  = s_whh + kb*12;
  const float* bias_b = s_bias + kb;

  #pragma unroll 1
  for (int t = 0; t < TSTEPS; t++){
    if (t + 1 < TSTEPS){
      const float2* src = (const float2*)(word + ((size_t)(t+1)*Bn + blockElem) * INF);
      uint32_t dst = sx0 + (uint32_t)(((t+1)&1) * (32*INF*4));
      #pragma unroll
      for (int m = 0; m < 14; m++){
        int i2 = m*32 + tid;
        if (i2 < 432) cp8(dst + (uint32_t)(i2*8), src + i2);
      }
      asm volatile("cp.async.commit_group;");
      asm volatile("cp.async.wait_group 1;");
    } else {
      asm volatile("cp.async.wait_group 0;");
    }
    __syncwarp();   // all lanes' cp.async for buffer t complete before reads

    // x rows for pair elements 2p and 2p+1 (both lanes of a pair read the
    // same addresses -> 2-way broadcast; row stride 27 coprime w/ 32 banks)
    const float* xbA = &s_x[t & 1][(2*p    ) * INF];
    const float* xbB = &s_x[t & 1][(2*p + 1) * INF];
    float xA[27], xB[27];
    #pragma unroll
    for (int j = 0; j < 27; j++){ xA[j] = xbA[j]; xB[j] = xbB[j]; }

    float hnA[5], hnB[5];
    #pragma unroll
    for (int kk = 0; kk < 5; kk++){
      float ai0 = bias_b[kk],      ai1 = ai0;
      float af0 = bias_b[kk + 10], af1 = af0;
      float ag0 = bias_b[kk + 20], ag1 = ag0;
      float ao0 = bias_b[kk + 30], ao1 = ao0;
      #pragma unroll
      for (int j = 0; j < 27; j++){
        float wi = wih_b[(kk     )*28 + j];
        float wf = wih_b[(kk + 10)*28 + j];
        float wg = wih_b[(kk + 20)*28 + j];
        float wo = wih_b[(kk + 30)*28 + j];
        float xa = xA[j], xb = xB[j];
        ai0 = fmaf(wi, xa, ai0);  ai1 = fmaf(wi, xb, ai1);
        af0 = fmaf(wf, xa, af0);  af1 = fmaf(wf, xb, af1);
        ag0 = fmaf(wg, xa, ag0);  ag1 = fmaf(wg, xb, ag1);
        ao0 = fmaf(wo, xa, ao0);  ao1 = fmaf(wo, xb, ao1);
      }
      #pragma unroll
      for (int j = 0; j < 10; j++){
        float ui = whh_b[(kk     )*12 + j];
        float uf = whh_b[(kk + 10)*12 + j];
        float ug = whh_b[(kk + 20)*12 + j];
        float uo = whh_b[(kk + 30)*12 + j];
        float ha = hA[j], hb = hB[j];
        ai0 = fmaf(ui, ha, ai0);  ai1 = fmaf(ui, hb, ai1);
        af0 = fmaf(uf, ha, af0);  af1 = fmaf(uf, hb, af1);
        ag0 = fmaf(ug, ha, ag0);  ag1 = fmaf(ug, hb, ag1);
        ao0 = fmaf(uo, ha, ao0);  ao1 = fmaf(uo, hb, ao1);
      }
      // activations: i/f/o accs hold x/2 (pre-halved weights) -> 1 MUFU + 1 FMA
      float i0 = sig_from_half(ai0), i1 = sig_from_half(ai1);
      float f0 = sig_from_half(af0), f1 = sig_from_half(af1);
      float g0 = tanh_fast(ag0),     g1 = tanh_fast(ag1);
      float o0 = sig_from_half(ao0), o1 = sig_from_half(ao1);
      float cn0 = fmaf(f0, cA[kk], i0*g0);
      float cn1 = fmaf(f1, cB[kk], i1*g1);
      float hv0 = o0 * tanh_fast(cn0);
      float hv1 = o1 * tanh_fast(cn1);
      cA[kk]  = fmaxf(cn0, 0.f);       // ReLU on carried cell state
      cB[kk]  = fmaxf(cn1, 0.f);
      hnA[kk] = fmaxf(hv0, 0.f);       // ReLU on carried hidden
      hnB[kk] = fmaxf(hv1, 0.f);
    }
    // exchange halves with pair partner -> full h for both elements
    const int ob = 5 - kb;             // partner's k-base (0 <-> 5)
    #pragma unroll
    for (int kk = 0; kk < 5; kk++){
      float oA = __shfl_xor_sync(0xFFFFFFFFu, hnA[kk], 1);
      float oB = __shfl_xor_sync(0xFFFFFFFFu, hnB[kk], 1);
      hA[kb + kk] = hnA[kk];  hA[ob + kk] = oA;
      hB[kb + kk] = hnB[kk];  hB[ob + kk] = oB;
    }
    // no barrier: buffer overwritten next iteration was last read by this
    // warp itself (warp-synchronous ordering via the __syncwarp above).
  }

  // ---- head: FC(10->5) -> ReLU -> Linear(5->1) -> sigmoid ----
  if (half == 0){
    float z0 = s_bout[0], z1 = s_bout[0];
    #pragma unroll
    for (int u = 0; u < 5; u++){
      float y0 = s_bfc[u], y1 = s_bfc[u];
      #pragma unroll
      for (int k = 0; k < 10; k++){
        float w = s_wfc[u*10 + k];
        y0 = fmaf(w, hA[k], y0);
        y1 = fmaf(w, hB[k], y1);
      }
      z0 = fmaf(s_wout[u], fmaxf(y0, 0.f), z0);
      z1 = fmaf(s_wout[u], fmaxf(y1, 0.f), z1);
    }
    const int b0 = blockElem + 2*p;
    // final sigmoid (z not pre-halved): 0.5 + 0.5*tanh(z/2)
    if (b0 + 1 < Bn){
      float2 v;
      v.x = fmaf(0.5f, tanh_fast(0.5f * z0), 0.5f);
      v.y = fmaf(0.5f, tanh_fast(0.5f * z1), 0.5f);
      *(float2*)(out + b0) = v;                 // coalesced 8B store
    } else if (b0 < Bn){
      out[b0] = fmaf(0.5f, tanh_fast(0.5f * z0), 0.5f);
    }
  }
}

extern "C" void kernel_launch(void* const* d_in, const int* in_sizes, int n_in,
                              void* d_out, int out_size) {
  const float* word  = (const float*)d_in[0];
  const float* W_ih  = (const float*)d_in[1];
  const float* W_hh  = (const float*)d_in[2];
  const float* b_ih  = (const float*)d_in[3];
  const float* b_hh  = (const float*)d_in[4];
  const float* W_fc  = (const float*)d_in[5];
  const float* b_fc  = (const float*)d_in[6];
  const float* W_out = (const float*)d_in[7];
  const float* b_out = (const float*)d_in[8];
  float* out = (float*)d_out;

  const int Bn = in_sizes[0] / (TSTEPS * INF);   // 65536
  const int blocks = (Bn + 31) / 32;             // 2048 single-warp blocks

  lstm_fused_kernel<<<blocks, 32>>>(word, W_ih, W_hh, b_ih, b_hh,
                                    W_fc, b_fc, W_out, b_out, out, Bn);
}